// round 2
// baseline (speedup 1.0000x reference)
#include <cuda_runtime.h>
#include <cuda_bf16.h>

// Problem constants
#define BB 8
#define NN 512
#define DD 64
#define EE 32

// Scratch: projections (allocation-free rule -> __device__ globals)
__device__ float g_src [BB * NN * EE];   // src[b,n,e]
__device__ float g_dstb[BB * NN * EE];   // dst[b,n,e] + be[e]

// ---------------------------------------------------------------------------
// Kernel 1: src = x @ We[:D], dstb = x @ We[D:] + be
// Block handles 8 rows (b,n). 64 threads: tid<32 -> src lanes e, tid>=32 -> dst.
// ---------------------------------------------------------------------------
__global__ __launch_bounds__(64) void proj_kernel(
    const float* __restrict__ x,
    const float* __restrict__ We,
    const float* __restrict__ be)
{
    const int row0 = blockIdx.x * 8;            // first (b*N+n) row
    __shared__ float xs[8][DD];

    const int tid = threadIdx.x;
    // load 8 x-rows (512 floats) coalesced
    #pragma unroll
    for (int k = 0; k < 8; k++) {
        int idx = k * 64 + tid;
        xs[idx >> 6][idx & 63] = x[row0 * DD + idx];
    }
    __syncthreads();

    const int e    = tid & 31;
    const int half = tid >> 5;                  // 0 = src, 1 = dst
    const float* W = We + half * DD * EE;
    const float bias = half ? be[e] : 0.0f;

    float acc[8];
    #pragma unroll
    for (int r = 0; r < 8; r++) acc[r] = bias;

    #pragma unroll 16
    for (int d = 0; d < DD; d++) {
        float w = W[d * EE + e];                // coalesced, L1/L2-hot (16KB total)
        #pragma unroll
        for (int r = 0; r < 8; r++)
            acc[r] = fmaf(xs[r][d], w, acc[r]); // xs broadcast across warp
    }

    float* dst = half ? g_dstb : g_src;
    #pragma unroll
    for (int r = 0; r < 8; r++)
        dst[(row0 + r) * EE + e] = acc[r];      // coalesced 128B stores
}

// ---------------------------------------------------------------------------
// Kernel 2: out[b,j] = sum_{i,e} relu(src[b,i,e] + dstb[b,j,e]) * Wr[i*E+e] + br
// Grid: (N/32, B). Block: 256 threads = 8 warps. Warp w handles 4 j's.
// lane = e. Stage src/Wr i-tiles (128 rows) in smem, reuse across 32 j's.
// ---------------------------------------------------------------------------
#define JT 32      // j's per block
#define JR 4       // j's per warp (register tile)
#define IT 128     // i's per smem tile

__global__ __launch_bounds__(256) void edge_reduce_kernel(
    const float* __restrict__ Wr,
    const float* __restrict__ br,
    float* __restrict__ out)
{
    const int b  = blockIdx.y;
    const int jb = blockIdx.x;                  // j-block
    const int tid  = threadIdx.x;
    const int lane = tid & 31;                  // = e
    const int w    = tid >> 5;                  // warp id 0..7

    __shared__ float src_sh[IT * EE];           // 16 KB
    __shared__ float wr_sh [IT * EE];           // 16 KB
    __shared__ float dst_sh[JT * EE];           // 4 KB

    // stage the 32 dstb rows this block owns
    for (int k = tid; k < JT * EE; k += 256)
        dst_sh[k] = g_dstb[(b * NN + jb * JT) * EE + k];
    __syncthreads();

    float dreg[JR], acc[JR];
    #pragma unroll
    for (int r = 0; r < JR; r++) {
        dreg[r] = dst_sh[(w * JR + r) * EE + lane];
        acc[r]  = 0.0f;
    }

    const float4* src_g = (const float4*)(g_src + b * NN * EE);
    const float4* wr_g  = (const float4*)Wr;

    for (int it = 0; it < NN; it += IT) {
        __syncthreads();                        // previous tile fully consumed
        // stage src & Wr tiles: 4096 floats each, float4 coalesced
        const int base4 = it * EE / 4;
        #pragma unroll
        for (int k = tid; k < IT * EE / 4; k += 256) {
            ((float4*)src_sh)[k] = src_g[base4 + k];
            ((float4*)wr_sh )[k] = wr_g [base4 + k];
        }
        __syncthreads();

        #pragma unroll 8
        for (int i = 0; i < IT; i++) {
            float s  = src_sh[i * EE + lane];   // conflict-free (stride 32)
            float wv = wr_sh [i * EE + lane];
            #pragma unroll
            for (int r = 0; r < JR; r++)
                acc[r] = fmaf(fmaxf(s + dreg[r], 0.0f), wv, acc[r]);
        }
    }

    // reduce over lanes (the e dimension + per-lane partial i-sums)
    #pragma unroll
    for (int r = 0; r < JR; r++) {
        #pragma unroll
        for (int off = 16; off; off >>= 1)
            acc[r] += __shfl_xor_sync(0xFFFFFFFFu, acc[r], off);
    }

    if (lane == 0) {
        const float brv = br[0];
        #pragma unroll
        for (int r = 0; r < JR; r++)
            out[b * NN + jb * JT + w * JR + r] = acc[r] + brv;
    }
}

// ---------------------------------------------------------------------------
// launch
// ---------------------------------------------------------------------------
extern "C" void kernel_launch(void* const* d_in, const int* in_sizes, int n_in,
                              void* d_out, int out_size)
{
    const float* x  = (const float*)d_in[0];   // (8,512,64)
    const float* We = (const float*)d_in[1];   // (128,32)
    const float* be = (const float*)d_in[2];   // (32,)
    const float* Wr = (const float*)d_in[3];   // (16384,1)
    const float* br = (const float*)d_in[4];   // (1,)
    float* out = (float*)d_out;                // (8,512,1)

    proj_kernel<<<BB * NN / 8, 64>>>(x, We, be);

    dim3 grid(NN / JT, BB);
    edge_reduce_kernel<<<grid, 256>>>(Wr, br, out);
}

// round 3
// speedup vs baseline: 1.1115x; 1.1115x over previous
#include <cuda_runtime.h>
#include <cuda_bf16.h>

// Problem constants
#define BB 8
#define NN 512
#define DD 64
#define EE 32

#define JT 32                 // j's per block
#define JR 4                  // j's per warp
#define SS 8                  // i-splits
#define IT (NN / SS)          // 64 i-rows per block

// Scratch (allocation-free rule -> __device__ globals)
__device__ float g_src [BB * NN * EE];        // src[b,n,e]
__device__ float g_dstb[BB * NN * EE];        // dst[b,n,e] + be[e]
__device__ float g_part[BB * NN * SS];        // partial[b,j,s]

// ---------------------------------------------------------------------------
// Kernel 1: src = x @ We[:D], dstb = x @ We[D:] + be
// ---------------------------------------------------------------------------
__global__ __launch_bounds__(64) void proj_kernel(
    const float* __restrict__ x,
    const float* __restrict__ We,
    const float* __restrict__ be)
{
    const int row0 = blockIdx.x * 8;            // first (b*N+n) row
    __shared__ float xs[8][DD];

    const int tid = threadIdx.x;
    #pragma unroll
    for (int k = 0; k < 8; k++) {
        int idx = k * 64 + tid;
        xs[idx >> 6][idx & 63] = x[row0 * DD + idx];
    }
    __syncthreads();

    const int e    = tid & 31;
    const int half = tid >> 5;                  // 0 = src, 1 = dst
    const float* W = We + half * DD * EE;
    const float bias = half ? be[e] : 0.0f;

    float acc[8];
    #pragma unroll
    for (int r = 0; r < 8; r++) acc[r] = bias;

    #pragma unroll 16
    for (int d = 0; d < DD; d++) {
        float w = W[d * EE + e];
        #pragma unroll
        for (int r = 0; r < 8; r++)
            acc[r] = fmaf(xs[r][d], w, acc[r]);
    }

    float* dst = half ? g_dstb : g_src;
    #pragma unroll
    for (int r = 0; r < 8; r++)
        dst[(row0 + r) * EE + e] = acc[r];
}

// ---------------------------------------------------------------------------
// Kernel 2: partial[b,j,s] = sum_{i in tile s, e} relu(src[b,i,e]+dstb[b,j,e])*Wr[i*E+e]
// Grid: (N/JT, B, SS). Block: 256 threads = 8 warps, warp w owns 4 j's, lane = e.
// One i-tile of 64 rows per block: single sync, no tile loop.
// ---------------------------------------------------------------------------
__global__ __launch_bounds__(256) void edge_reduce_kernel(
    const float* __restrict__ Wr,
    float* __restrict__ part)
{
    const int b  = blockIdx.y;
    const int jb = blockIdx.x;
    const int s  = blockIdx.z;
    const int tid  = threadIdx.x;
    const int lane = tid & 31;                  // = e
    const int w    = tid >> 5;                  // warp 0..7

    __shared__ float src_sh[IT * EE];           // 8 KB
    __shared__ float wr_sh [IT * EE];           // 8 KB
    __shared__ float dst_sh[JT * EE];           // 4 KB

    // stage dst rows (32x32), src/Wr i-tile (64x32 each), float4 coalesced
    {
        const float4* dst_g = (const float4*)(g_dstb + (b * NN + jb * JT) * EE);
        ((float4*)dst_sh)[tid] = dst_g[tid];    // 256 float4 = exactly one per thread

        const float4* src_g = (const float4*)(g_src + (b * NN + s * IT) * EE);
        const float4* wr_g  = (const float4*)(Wr + s * IT * EE);
        #pragma unroll
        for (int k = 0; k < IT * EE / 4 / 256; k++) {   // 2 iters
            ((float4*)src_sh)[k * 256 + tid] = src_g[k * 256 + tid];
            ((float4*)wr_sh )[k * 256 + tid] = wr_g [k * 256 + tid];
        }
    }
    __syncthreads();

    float dreg[JR], acc[JR];
    #pragma unroll
    for (int r = 0; r < JR; r++) {
        dreg[r] = dst_sh[(w * JR + r) * EE + lane];
        acc[r]  = 0.0f;
    }

    #pragma unroll 8
    for (int i = 0; i < IT; i++) {
        float sv = src_sh[i * EE + lane];        // conflict-free (stride 32)
        float wv = wr_sh [i * EE + lane];
        #pragma unroll
        for (int r = 0; r < JR; r++)
            acc[r] = fmaf(fmaxf(sv + dreg[r], 0.0f), wv, acc[r]);
    }

    // reduce across lanes (e dim + per-lane partial i-sums)
    #pragma unroll
    for (int r = 0; r < JR; r++) {
        #pragma unroll
        for (int off = 16; off; off >>= 1)
            acc[r] += __shfl_xor_sync(0xFFFFFFFFu, acc[r], off);
    }

    if (lane == 0) {
        const int j = jb * JT + w * JR;
        #pragma unroll
        for (int r = 0; r < JR; r++)
            part[(b * NN + j + r) * SS + s] = acc[r];
    }
}

// ---------------------------------------------------------------------------
// Kernel 3: out[b,j] = sum_s partial[b,j,s] + br
// ---------------------------------------------------------------------------
__global__ __launch_bounds__(256) void final_reduce_kernel(
    const float* __restrict__ part,
    const float* __restrict__ br,
    float* __restrict__ out)
{
    const int idx = blockIdx.x * 256 + threadIdx.x;   // b*N + j, 0..4095
    const float4* p = (const float4*)(part + idx * SS);
    float4 a = p[0];
    float4 c = p[1];
    out[idx] = (a.x + a.y) + (a.z + a.w) + (c.x + c.y) + (c.z + c.w) + br[0];
}

// ---------------------------------------------------------------------------
// launch
// ---------------------------------------------------------------------------
extern "C" void kernel_launch(void* const* d_in, const int* in_sizes, int n_in,
                              void* d_out, int out_size)
{
    const float* x  = (const float*)d_in[0];   // (8,512,64)
    const float* We = (const float*)d_in[1];   // (128,32)
    const float* be = (const float*)d_in[2];   // (32,)
    const float* Wr = (const float*)d_in[3];   // (16384,1)
    const float* br = (const float*)d_in[4];   // (1,)
    float* out = (float*)d_out;                // (8,512,1)

    float* partp;
    cudaGetSymbolAddress((void**)&partp, g_part);

    proj_kernel<<<BB * NN / 8, 64>>>(x, We, be);

    dim3 grid(NN / JT, BB, SS);
    edge_reduce_kernel<<<grid, 256>>>(Wr, partp);

    final_reduce_kernel<<<BB * NN / 256, 256>>>(partp, br, out);
}